// round 2
// baseline (speedup 1.0000x reference)
#include <cuda_runtime.h>
#include <cuda_bf16.h>
#include <cstdint>

// Problem constants (match reference setup_inputs)
#define NQ    10000
#define NV    19560
#define EMB   256
#define HEADS 8
#define LVLS  4
#define PTS   8
#define DHEAD 32   // EMB / HEADS

// level shapes / flat starts (spatial_shapes is static in the reference)
__device__ __constant__ int c_H[4]      = {92, 46, 23, 12};
__device__ __constant__ int c_W[4]      = {160, 80, 40, 20};
__device__ __constant__ int c_start[4]  = {0, 14720, 18400, 19320};

// Scratch (static __device__ arrays — no allocation allowed)
__device__ float g_q[NQ * EMB];        // query + query_pos
__device__ float g_v[NV * EMB];        // value @ W_val + b_val
__device__ float g_off[NQ * 512];      // sampling offsets
__device__ float g_logits[NQ * 256];   // attention logits
__device__ float g_samp[NQ * EMB];     // aggregated sampled values

// ---------------------------------------------------------------------------
// q = query + query_pos
// ---------------------------------------------------------------------------
__global__ void add_kernel(const float* __restrict__ a, const float* __restrict__ b) {
    int i = blockIdx.x * blockDim.x + threadIdx.x;
    if (i < NQ * EMB) g_q[i] = a[i] + b[i];
}

// ---------------------------------------------------------------------------
// Tiled fp32 GEMM: C[M,N] = A[M,K] @ B[K,N] + bias[N] (+ add[M,N])
// BM=BN=64, BK=16, 256 threads, 4x4 per-thread tile.
// ---------------------------------------------------------------------------
__global__ void gemm64_kernel(const float* __restrict__ A, const float* __restrict__ B,
                              const float* __restrict__ bias, const float* __restrict__ add,
                              float* __restrict__ C, int M, int N, int K)
{
    __shared__ float As[16][65];   // [k][row], padded vs bank conflicts
    __shared__ float Bs[16][68];   // [k][col], 16B-aligned row stride for float4

    const int block_row = blockIdx.y * 64;
    const int block_col = blockIdx.x * 64;
    const int tid = threadIdx.x;
    const int tx = tid & 15;        // 0..15 -> 4 output cols each
    const int ty = tid >> 4;        // 0..15 -> 4 output rows each

    // load mapping
    const int ar = tid >> 2;            // A tile row 0..63
    const int ak = (tid & 3) * 4;       // A tile k offset 0,4,8,12
    const int br = tid >> 4;            // B tile k row 0..15
    const int bc = (tid & 15) * 4;      // B tile col offset

    float acc[4][4] = {};

    for (int k0 = 0; k0 < K; k0 += 16) {
        float4 av = make_float4(0.f, 0.f, 0.f, 0.f);
        if (block_row + ar < M)
            av = *(const float4*)&A[(size_t)(block_row + ar) * K + k0 + ak];
        As[ak + 0][ar] = av.x;
        As[ak + 1][ar] = av.y;
        As[ak + 2][ar] = av.z;
        As[ak + 3][ar] = av.w;

        float4 bv = *(const float4*)&B[(size_t)(k0 + br) * N + block_col + bc];
        *(float4*)&Bs[br][bc] = bv;

        __syncthreads();

        #pragma unroll
        for (int kk = 0; kk < 16; kk++) {
            float a[4], b[4];
            #pragma unroll
            for (int i = 0; i < 4; i++) a[i] = As[kk][ty * 4 + i];
            #pragma unroll
            for (int j = 0; j < 4; j++) b[j] = Bs[kk][tx * 4 + j];
            #pragma unroll
            for (int i = 0; i < 4; i++)
                #pragma unroll
                for (int j = 0; j < 4; j++)
                    acc[i][j] = fmaf(a[i], b[j], acc[i][j]);
        }
        __syncthreads();
    }

    #pragma unroll
    for (int i = 0; i < 4; i++) {
        int row = block_row + ty * 4 + i;
        if (row >= M) continue;
        #pragma unroll
        for (int j = 0; j < 4; j++) {
            int col = block_col + tx * 4 + j;
            float r = acc[i][j] + bias[col];
            if (add) r += add[(size_t)row * N + col];
            C[(size_t)row * N + col] = r;
        }
    }
}

// ---------------------------------------------------------------------------
// Deformable sampling + warp softmax. One warp per (query, head).
// Lane s (0..31) owns sample s = l*8+p for coord/weight computation;
// for accumulation each lane owns channel c = lane, samples broadcast via shfl.
// ---------------------------------------------------------------------------
__global__ void sampler_kernel(const float* __restrict__ refp)
{
    const int q    = blockIdx.x;          // one block = one query, 8 warps = 8 heads
    const int h    = threadIdx.x >> 5;
    const int lane = threadIdx.x & 31;

    // ---- per-lane sample s = lane: coords + softmax weight ----
    const int s = lane;
    const int l = s >> 3;
    const int p = s & 7;
    const int z = p & 3;                  // Z-anchor index (P//Z=2, Z=4 -> z = p % 4)

    const float ox = g_off[(size_t)q * 512 + h * 64 + s * 2 + 0];
    const float oy = g_off[(size_t)q * 512 + h * 64 + s * 2 + 1];
    const float rx = refp[(size_t)q * 8 + z * 2 + 0];
    const float ry = refp[(size_t)q * 8 + z * 2 + 1];
    const int   Wl = c_W[l], Hl = c_H[l];
    // (ref + off/W)*W - 0.5 == ref*W + off - 0.5
    const float x = rx * (float)Wl + ox - 0.5f;
    const float y = ry * (float)Hl + oy - 0.5f;

    float logit = g_logits[(size_t)q * 256 + h * 32 + s];
    // warp softmax over the 32 samples of this head
    float m = logit;
    #pragma unroll
    for (int o = 16; o > 0; o >>= 1) m = fmaxf(m, __shfl_xor_sync(0xffffffffu, m, o));
    float e = __expf(logit - m);
    float sum = e;
    #pragma unroll
    for (int o = 16; o > 0; o >>= 1) sum += __shfl_xor_sync(0xffffffffu, sum, o);
    const float w = e / sum;

    // ---- accumulation: lane = channel c, loop over 32 samples ----
    const int c = lane;
    float acc = 0.f;

    #pragma unroll 4
    for (int s2 = 0; s2 < 32; s2++) {
        const float xs = __shfl_sync(0xffffffffu, x, s2);
        const float ys = __shfl_sync(0xffffffffu, y, s2);
        const float ws = __shfl_sync(0xffffffffu, w, s2);
        const int   ls = s2 >> 3;
        const int   W2 = c_W[ls], H2 = c_H[ls];
        const int   base = c_start[ls];

        const float x0f = floorf(xs), y0f = floorf(ys);
        const int   x0 = (int)x0f,    y0 = (int)y0f;
        const float lx = xs - x0f,    ly = ys - y0f;

        const float w00 = (1.f - lx) * (1.f - ly);
        const float w10 = lx * (1.f - ly);
        const float w01 = (1.f - lx) * ly;
        const float w11 = lx * ly;

        const bool vx0 = (x0 >= 0) & (x0 < W2);
        const bool vx1 = (x0 + 1 >= 0) & (x0 + 1 < W2);
        const bool vy0 = (y0 >= 0) & (y0 < H2);
        const bool vy1 = (y0 + 1 >= 0) & (y0 + 1 < H2);

        const size_t coff = (size_t)h * DHEAD + c;
        if (vx0 & vy0)
            acc += ws * w00 * g_v[(size_t)(base + y0 * W2 + x0) * EMB + coff];
        if (vx1 & vy0)
            acc += ws * w10 * g_v[(size_t)(base + y0 * W2 + x0 + 1) * EMB + coff];
        if (vx0 & vy1)
            acc += ws * w01 * g_v[(size_t)(base + (y0 + 1) * W2 + x0) * EMB + coff];
        if (vx1 & vy1)
            acc += ws * w11 * g_v[(size_t)(base + (y0 + 1) * W2 + x0 + 1) * EMB + coff];
    }

    g_samp[(size_t)q * EMB + h * DHEAD + c] = acc;
}

// ---------------------------------------------------------------------------
// Launch
// ---------------------------------------------------------------------------
static float* sym_addr(const void* symbol) {
    void* p = nullptr;
    cudaGetSymbolAddress(&p, symbol);
    return (float*)p;
}

extern "C" void kernel_launch(void* const* d_in, const int* in_sizes, int n_in,
                              void* d_out, int out_size)
{
    const float* query  = (const float*)d_in[0];
    const float* value  = (const float*)d_in[1];
    const float* qpos   = (const float*)d_in[2];
    const float* refp   = (const float*)d_in[3];
    // d_in[4] spatial_shapes: static, baked into constants
    const float* W_off  = (const float*)d_in[5];
    const float* b_off  = (const float*)d_in[6];
    const float* W_attn = (const float*)d_in[7];
    const float* b_attn = (const float*)d_in[8];
    const float* W_val  = (const float*)d_in[9];
    const float* b_val  = (const float*)d_in[10];
    const float* W_out  = (const float*)d_in[11];
    const float* b_out  = (const float*)d_in[12];
    float* out = (float*)d_out;

    float* qb   = sym_addr(g_q);
    float* vb   = sym_addr(g_v);
    float* offb = sym_addr(g_off);
    float* logb = sym_addr(g_logits);
    float* sampb= sym_addr(g_samp);

    // 1. q = query + query_pos
    add_kernel<<<(NQ * EMB + 255) / 256, 256>>>(query, qpos);

    // 2. v = value @ W_val + b_val   [19560 x 256]
    {
        dim3 grid(EMB / 64, (NV + 63) / 64);
        gemm64_kernel<<<grid, 256>>>(value, W_val, b_val, nullptr, vb, NV, EMB, EMB);
    }
    // 3. off = q @ W_off + b_off     [10000 x 512]
    {
        dim3 grid(512 / 64, (NQ + 63) / 64);
        gemm64_kernel<<<grid, 256>>>(qb, W_off, b_off, nullptr, offb, NQ, 512, EMB);
    }
    // 4. logits = q @ W_attn + b_attn [10000 x 256]
    {
        dim3 grid(256 / 64, (NQ + 63) / 64);
        gemm64_kernel<<<grid, 256>>>(qb, W_attn, b_attn, nullptr, logb, NQ, 256, EMB);
    }
    // 5. deformable sampling (softmax fused in-warp)
    sampler_kernel<<<NQ, 256>>>(refp);

    // 6. out = samp @ W_out + b_out + query (residual)
    {
        dim3 grid(EMB / 64, (NQ + 63) / 64);
        gemm64_kernel<<<grid, 256>>>(sampb, W_out, b_out, query, out, NQ, EMB, EMB);
    }
}

// round 4
// speedup vs baseline: 1.3067x; 1.3067x over previous
#include <cuda_runtime.h>
#include <cuda_bf16.h>
#include <cstdint>

// Problem constants (match reference setup_inputs)
#define NQ    10000
#define NV    19560
#define EMB   256
#define HEADS 8
#define LVLS  4
#define PTS   8
#define DHEAD 32   // EMB / HEADS

// level shapes / flat starts (spatial_shapes is static in the reference)
__device__ __constant__ int c_H[4]      = {92, 46, 23, 12};
__device__ __constant__ int c_W[4]      = {160, 80, 40, 20};
__device__ __constant__ int c_start[4]  = {0, 14720, 18400, 19320};

// Scratch (static __device__ arrays — no allocation allowed)
__device__ float g_v[NV * EMB];        // value @ W_val + b_val
__device__ float g_off[NQ * 512];      // sampling offsets
__device__ float g_logits[NQ * 256];   // attention logits
__device__ float g_samp[NQ * EMB];     // aggregated sampled values

// ---------------------------------------------------------------------------
// Tiled fp32 GEMM: C[M,N] = (A (+A2))[M,K] @ B[K,N] + bias[N] (+ add[M,N])
// 128x128 tile, BK=16, 256 threads, 8x8 per-thread (split 4+4), double-buffered
// shared memory with register prefetch. N must be a multiple of 128, K of 16.
// ---------------------------------------------------------------------------
__global__ void __launch_bounds__(256, 2)
gemm128_kernel(const float* __restrict__ A, const float* __restrict__ A2,
               const float* __restrict__ B,
               const float* __restrict__ bias, const float* __restrict__ add,
               float* __restrict__ C, int M, int N, int K)
{
    __shared__ float As[2][16][132];   // [buf][k][m], pad keeps 16B alignment
    __shared__ float Bs[2][16][132];   // [buf][k][n]

    const int block_row = blockIdx.y * 128;
    const int block_col = blockIdx.x * 128;
    const int tid = threadIdx.x;
    const int tx = tid & 15;           // output cols: tx*4 .. +3, and +64
    const int ty = tid >> 4;           // output rows: ty*4 .. +3, and +64

    // global load mapping
    const int am  = tid >> 1;              // A tile row 0..127
    const int akq = (tid & 1) * 8;         // A k offset: 0 or 8 (two float4 each)
    const int bk  = tid >> 4;              // B tile k row 0..15
    const int bc  = (tid & 15) * 4;        // B col offset (and +64)

    const int arow = min(block_row + am, M - 1);   // clamp; invalid rows never stored
    const float* Ap  = A  + (size_t)arow * K;
    const float* A2p = A2 ? A2 + (size_t)arow * K : nullptr;
    const float* Bp  = B + (size_t)bk * N + block_col + bc;   // BUGFIX: include bc

    float acc[8][8] = {};
    float4 pa0, pa1, pb0, pb1;

    // --- load tile 0 ---
    {
        pa0 = *(const float4*)&Ap[akq];
        pa1 = *(const float4*)&Ap[akq + 4];
        if (A2p) {
            float4 q0 = *(const float4*)&A2p[akq];
            float4 q1 = *(const float4*)&A2p[akq + 4];
            pa0.x += q0.x; pa0.y += q0.y; pa0.z += q0.z; pa0.w += q0.w;
            pa1.x += q1.x; pa1.y += q1.y; pa1.z += q1.z; pa1.w += q1.w;
        }
        pb0 = *(const float4*)&Bp[0];
        pb1 = *(const float4*)&Bp[64];
        As[0][akq + 0][am] = pa0.x;  As[0][akq + 1][am] = pa0.y;
        As[0][akq + 2][am] = pa0.z;  As[0][akq + 3][am] = pa0.w;
        As[0][akq + 4][am] = pa1.x;  As[0][akq + 5][am] = pa1.y;
        As[0][akq + 6][am] = pa1.z;  As[0][akq + 7][am] = pa1.w;
        *(float4*)&Bs[0][bk][bc]      = pb0;
        *(float4*)&Bs[0][bk][bc + 64] = pb1;
    }
    __syncthreads();

    int buf = 0;
    for (int k0 = 0; k0 < K; k0 += 16) {
        const bool last = (k0 + 16 >= K);
        if (!last) {
            pa0 = *(const float4*)&Ap[k0 + 16 + akq];
            pa1 = *(const float4*)&Ap[k0 + 16 + akq + 4];
            if (A2p) {
                float4 q0 = *(const float4*)&A2p[k0 + 16 + akq];
                float4 q1 = *(const float4*)&A2p[k0 + 16 + akq + 4];
                pa0.x += q0.x; pa0.y += q0.y; pa0.z += q0.z; pa0.w += q0.w;
                pa1.x += q1.x; pa1.y += q1.y; pa1.z += q1.z; pa1.w += q1.w;
            }
            pb0 = *(const float4*)&Bp[(size_t)(k0 + 16) * N];
            pb1 = *(const float4*)&Bp[(size_t)(k0 + 16) * N + 64];
        }

        const float (*Asb)[132] = As[buf];
        const float (*Bsb)[132] = Bs[buf];
        #pragma unroll
        for (int kk = 0; kk < 16; kk++) {
            float4 a0 = *(const float4*)&Asb[kk][ty * 4];
            float4 a1 = *(const float4*)&Asb[kk][64 + ty * 4];
            float4 b0 = *(const float4*)&Bsb[kk][tx * 4];
            float4 b1 = *(const float4*)&Bsb[kk][64 + tx * 4];
            float av[8] = {a0.x, a0.y, a0.z, a0.w, a1.x, a1.y, a1.z, a1.w};
            float bv[8] = {b0.x, b0.y, b0.z, b0.w, b1.x, b1.y, b1.z, b1.w};
            #pragma unroll
            for (int i = 0; i < 8; i++)
                #pragma unroll
                for (int j = 0; j < 8; j++)
                    acc[i][j] = fmaf(av[i], bv[j], acc[i][j]);
        }

        if (!last) {
            const int nb = buf ^ 1;
            As[nb][akq + 0][am] = pa0.x;  As[nb][akq + 1][am] = pa0.y;
            As[nb][akq + 2][am] = pa0.z;  As[nb][akq + 3][am] = pa0.w;
            As[nb][akq + 4][am] = pa1.x;  As[nb][akq + 5][am] = pa1.y;
            As[nb][akq + 6][am] = pa1.z;  As[nb][akq + 7][am] = pa1.w;
            *(float4*)&Bs[nb][bk][bc]      = pb0;
            *(float4*)&Bs[nb][bk][bc + 64] = pb1;
            __syncthreads();
            buf = nb;
        }
    }

    // epilogue
    #pragma unroll
    for (int ih = 0; ih < 2; ih++) {
        #pragma unroll
        for (int i = 0; i < 4; i++) {
            const int row = block_row + ih * 64 + ty * 4 + i;
            if (row >= M) continue;
            #pragma unroll
            for (int jh = 0; jh < 2; jh++) {
                const int col = block_col + jh * 64 + tx * 4;
                float4 r;
                r.x = acc[ih * 4 + i][jh * 4 + 0] + bias[col + 0];
                r.y = acc[ih * 4 + i][jh * 4 + 1] + bias[col + 1];
                r.z = acc[ih * 4 + i][jh * 4 + 2] + bias[col + 2];
                r.w = acc[ih * 4 + i][jh * 4 + 3] + bias[col + 3];
                if (add) {
                    const float4 ad = *(const float4*)&add[(size_t)row * N + col];
                    r.x += ad.x; r.y += ad.y; r.z += ad.z; r.w += ad.w;
                }
                *(float4*)&C[(size_t)row * N + col] = r;
            }
        }
    }
}

// ---------------------------------------------------------------------------
// Deformable sampling + warp softmax. One warp per (query, head).
// Phase 1: lane s owns sample s (coords + softmax weight).
// Phase 2: lane = (group g = lane>>3, channels cl = (lane&7)*4); 8 iterations,
//          each handling 4 samples concurrently with float4 gathers; then
//          butterfly-reduce across groups and store float4 from lanes 0-7.
// ---------------------------------------------------------------------------
__global__ void sampler_kernel(const float* __restrict__ refp)
{
    const int q    = blockIdx.x;
    const int h    = threadIdx.x >> 5;
    const int lane = threadIdx.x & 31;

    // ---- per-lane sample s = lane: coords + softmax weight ----
    const int s = lane;
    const int l = s >> 3;
    const int p = s & 7;
    const int z = p & 3;

    const float ox = g_off[(size_t)q * 512 + h * 64 + s * 2 + 0];
    const float oy = g_off[(size_t)q * 512 + h * 64 + s * 2 + 1];
    const float rx = refp[(size_t)q * 8 + z * 2 + 0];
    const float ry = refp[(size_t)q * 8 + z * 2 + 1];
    // (ref + off/W)*W - 0.5 == ref*W + off - 0.5
    const float x = rx * (float)c_W[l] + ox - 0.5f;
    const float y = ry * (float)c_H[l] + oy - 0.5f;

    float logit = g_logits[(size_t)q * 256 + h * 32 + s];
    float m = logit;
    #pragma unroll
    for (int o = 16; o > 0; o >>= 1) m = fmaxf(m, __shfl_xor_sync(0xffffffffu, m, o));
    float e = __expf(logit - m);
    float sum = e;
    #pragma unroll
    for (int o = 16; o > 0; o >>= 1) sum += __shfl_xor_sync(0xffffffffu, sum, o);
    const float w = e / sum;

    // ---- accumulation ----
    const int g  = lane >> 3;          // sample group 0..3
    const int cl = (lane & 7) * 4;     // channel quad 0,4,...,28
    float4 acc = make_float4(0.f, 0.f, 0.f, 0.f);
    const size_t coff = (size_t)h * DHEAD + cl;

    #pragma unroll
    for (int it = 0; it < 8; it++) {
        const int s2 = it * 4 + g;
        const float xs = __shfl_sync(0xffffffffu, x, s2);
        const float ys = __shfl_sync(0xffffffffu, y, s2);
        const float ws = __shfl_sync(0xffffffffu, w, s2);
        const int   ls = s2 >> 3;
        const int   W2 = c_W[ls], H2 = c_H[ls];
        const int   base = c_start[ls];

        const float x0f = floorf(xs), y0f = floorf(ys);
        const int   x0 = (int)x0f,    y0 = (int)y0f;
        const float lx = xs - x0f,    ly = ys - y0f;

        const float w00 = ws * (1.f - lx) * (1.f - ly);
        const float w10 = ws * lx * (1.f - ly);
        const float w01 = ws * (1.f - lx) * ly;
        const float w11 = ws * lx * ly;

        const bool vx0 = (x0 >= 0) & (x0 < W2);
        const bool vx1 = (x0 + 1 >= 0) & (x0 + 1 < W2);
        const bool vy0 = (y0 >= 0) & (y0 < H2);
        const bool vy1 = (y0 + 1 >= 0) & (y0 + 1 < H2);

        const float* row0 = g_v + ((size_t)(base + y0 * W2 + x0) * EMB + coff);
        const float* row1 = row0 + (size_t)W2 * EMB;

        if (vy0) {
            if (vx0) {
                const float4 t = *(const float4*)row0;
                acc.x = fmaf(w00, t.x, acc.x); acc.y = fmaf(w00, t.y, acc.y);
                acc.z = fmaf(w00, t.z, acc.z); acc.w = fmaf(w00, t.w, acc.w);
            }
            if (vx1) {
                const float4 t = *(const float4*)(row0 + EMB);
                acc.x = fmaf(w10, t.x, acc.x); acc.y = fmaf(w10, t.y, acc.y);
                acc.z = fmaf(w10, t.z, acc.z); acc.w = fmaf(w10, t.w, acc.w);
            }
        }
        if (vy1) {
            if (vx0) {
                const float4 t = *(const float4*)row1;
                acc.x = fmaf(w01, t.x, acc.x); acc.y = fmaf(w01, t.y, acc.y);
                acc.z = fmaf(w01, t.z, acc.z); acc.w = fmaf(w01, t.w, acc.w);
            }
            if (vx1) {
                const float4 t = *(const float4*)(row1 + EMB);
                acc.x = fmaf(w11, t.x, acc.x); acc.y = fmaf(w11, t.y, acc.y);
                acc.z = fmaf(w11, t.z, acc.z); acc.w = fmaf(w11, t.w, acc.w);
            }
        }
    }

    // reduce across the 4 sample-groups (lanes stride 8)
    #pragma unroll
    for (int o = 8; o < 32; o <<= 1) {
        acc.x += __shfl_xor_sync(0xffffffffu, acc.x, o);
        acc.y += __shfl_xor_sync(0xffffffffu, acc.y, o);
        acc.z += __shfl_xor_sync(0xffffffffu, acc.z, o);
        acc.w += __shfl_xor_sync(0xffffffffu, acc.w, o);
    }
    if (lane < 8)
        *(float4*)&g_samp[(size_t)q * EMB + h * DHEAD + cl] = acc;
}

// ---------------------------------------------------------------------------
// Launch
// ---------------------------------------------------------------------------
static float* sym_addr(const void* symbol) {
    void* p = nullptr;
    cudaGetSymbolAddress(&p, symbol);
    return (float*)p;
}

extern "C" void kernel_launch(void* const* d_in, const int* in_sizes, int n_in,
                              void* d_out, int out_size)
{
    const float* query  = (const float*)d_in[0];
    const float* value  = (const float*)d_in[1];
    const float* qpos   = (const float*)d_in[2];
    const float* refp   = (const float*)d_in[3];
    // d_in[4] spatial_shapes: static, baked into constants
    const float* W_off  = (const float*)d_in[5];
    const float* b_off  = (const float*)d_in[6];
    const float* W_attn = (const float*)d_in[7];
    const float* b_attn = (const float*)d_in[8];
    const float* W_val  = (const float*)d_in[9];
    const float* b_val  = (const float*)d_in[10];
    const float* W_out  = (const float*)d_in[11];
    const float* b_out  = (const float*)d_in[12];
    float* out = (float*)d_out;

    float* vb    = sym_addr(g_v);
    float* offb  = sym_addr(g_off);
    float* logb  = sym_addr(g_logits);
    float* sampb = sym_addr(g_samp);

    // 1. v = value @ W_val + b_val   [19560 x 256]
    {
        dim3 grid(EMB / 128, (NV + 127) / 128);
        gemm128_kernel<<<grid, 256>>>(value, nullptr, W_val, b_val, nullptr, vb, NV, EMB, EMB);
    }
    // 2. off = (query+qpos) @ W_off + b_off   [10000 x 512]  (q-add fused)
    {
        dim3 grid(512 / 128, (NQ + 127) / 128);
        gemm128_kernel<<<grid, 256>>>(query, qpos, W_off, b_off, nullptr, offb, NQ, 512, EMB);
    }
    // 3. logits = (query+qpos) @ W_attn + b_attn  [10000 x 256]
    {
        dim3 grid(256 / 128, (NQ + 127) / 128);
        gemm128_kernel<<<grid, 256>>>(query, qpos, W_attn, b_attn, nullptr, logb, NQ, 256, EMB);
    }
    // 4. deformable sampling (softmax fused in-warp)
    sampler_kernel<<<NQ, 256>>>(refp);

    // 5. out = samp @ W_out + b_out + query (residual)
    {
        dim3 grid(EMB / 128, (NQ + 127) / 128);
        gemm128_kernel<<<grid, 256>>>(sampb, nullptr, W_out, b_out, query, out, NQ, EMB, EMB);
    }
}

// round 5
// speedup vs baseline: 1.3590x; 1.0400x over previous
#include <cuda_runtime.h>
#include <cuda_bf16.h>
#include <cstdint>

// Problem constants (match reference setup_inputs)
#define NQ    10000
#define NV    19560
#define EMB   256
#define HEADS 8
#define LVLS  4
#define PTS   8
#define DHEAD 32   // EMB / HEADS

// level shapes / flat starts (spatial_shapes is static in the reference)
__device__ __constant__ int c_H[4]      = {92, 46, 23, 12};
__device__ __constant__ int c_W[4]      = {160, 80, 40, 20};
__device__ __constant__ int c_start[4]  = {0, 14720, 18400, 19320};

// Scratch (static __device__ arrays — no allocation allowed)
__device__ float g_v[NV * EMB];        // value @ W_val + b_val
__device__ float g_off[NQ * 512];      // sampling offsets
__device__ float g_logits[NQ * 256];   // attention logits
__device__ float g_samp[NQ * EMB];     // aggregated sampled values

__device__ __forceinline__ uint32_t f2tf32(float x) {
    uint32_t r;
    asm("cvt.rna.tf32.f32 %0, %1;" : "=r"(r) : "f"(x));
    return r;
}

// ---------------------------------------------------------------------------
// TF32 tensor-core GEMM: C[M,N] = (A (+A2))[M,K] @ B[K,N] + bias[N] (+ add)
// Block 128x128, BK=16, 256 threads = 8 warps (2x4), warp tile 64x32.
// mma.m16n8k8 tf32, fp32 accumulate. Double-buffered smem, conflict-free
// fragment strides (As: 20, Bs: 132). N % 128 == 0, K % 16 == 0 required.
// ---------------------------------------------------------------------------
#define AS_STR 20
#define BS_STR 132

__global__ void __launch_bounds__(256)
gemm_tf32_kernel(const float* __restrict__ A, const float* __restrict__ A2,
                 const float* __restrict__ B,
                 const float* __restrict__ bias, const float* __restrict__ add,
                 float* __restrict__ C, int M, int N, int K)
{
    __shared__ uint32_t As[2][128 * AS_STR];   // [m][k], tf32 bits
    __shared__ uint32_t Bs[2][16 * BS_STR];    // [k][n], tf32 bits

    const int tid  = threadIdx.x;
    const int wid  = tid >> 5;
    const int lane = tid & 31;
    const int warp_m = (wid >> 2) * 64;    // 0 / 64
    const int warp_n = (wid & 3) * 32;     // 0,32,64,96
    const int block_row = blockIdx.y * 128;
    const int block_col = blockIdx.x * 128;

    // global load mapping
    const int am  = tid >> 1;              // A tile row 0..127
    const int akq = (tid & 1) * 8;         // A k offset 0 / 8 (8 floats each)
    const int bk  = tid >> 4;              // B tile k row 0..15
    const int bc  = (tid & 15) * 4;        // B col offset (and +64)

    const int arow = min(block_row + am, M - 1);   // clamp; guarded at store
    const float* Ap  = A + (size_t)arow * K + akq;
    const float* A2p = A2 ? A2 + (size_t)arow * K + akq : nullptr;
    const float* Bp  = B + (size_t)bk * N + block_col + bc;

    float acc[4][4][4] = {};               // [mt][nt][frag]
    float pa[8];
    float4 pb0, pb1;

    auto load_g = [&](int k0) {
        float4 v0 = *(const float4*)&Ap[k0];
        float4 v1 = *(const float4*)&Ap[k0 + 4];
        if (A2p) {
            float4 q0 = *(const float4*)&A2p[k0];
            float4 q1 = *(const float4*)&A2p[k0 + 4];
            v0.x += q0.x; v0.y += q0.y; v0.z += q0.z; v0.w += q0.w;
            v1.x += q1.x; v1.y += q1.y; v1.z += q1.z; v1.w += q1.w;
        }
        pa[0] = v0.x; pa[1] = v0.y; pa[2] = v0.z; pa[3] = v0.w;
        pa[4] = v1.x; pa[5] = v1.y; pa[6] = v1.z; pa[7] = v1.w;
        pb0 = *(const float4*)&Bp[(size_t)k0 * N];
        pb1 = *(const float4*)&Bp[(size_t)k0 * N + 64];
    };
    auto store_s = [&](int b) {
        #pragma unroll
        for (int i = 0; i < 8; i++)
            As[b][am * AS_STR + akq + i] = f2tf32(pa[i]);
        uint4 u0, u1;
        u0.x = f2tf32(pb0.x); u0.y = f2tf32(pb0.y); u0.z = f2tf32(pb0.z); u0.w = f2tf32(pb0.w);
        u1.x = f2tf32(pb1.x); u1.y = f2tf32(pb1.y); u1.z = f2tf32(pb1.z); u1.w = f2tf32(pb1.w);
        *(uint4*)&Bs[b][bk * BS_STR + bc]      = u0;
        *(uint4*)&Bs[b][bk * BS_STR + bc + 64] = u1;
    };

    load_g(0);
    store_s(0);
    __syncthreads();

    int buf = 0;
    for (int k0 = 0; k0 < K; k0 += 16) {
        const bool last = (k0 + 16 >= K);
        if (!last) load_g(k0 + 16);

        const uint32_t* Asb = As[buf];
        const uint32_t* Bsb = Bs[buf];
        const int ar = warp_m + (lane >> 2);
        const int bn = warp_n + (lane >> 2);

        #pragma unroll
        for (int ks = 0; ks < 2; ks++) {
            const int kc = ks * 8 + (lane & 3);
            uint32_t af[4][4], bf[4][2];
            #pragma unroll
            for (int mt = 0; mt < 4; mt++) {
                const int r = ar + mt * 16;
                af[mt][0] = Asb[r * AS_STR + kc];
                af[mt][1] = Asb[(r + 8) * AS_STR + kc];
                af[mt][2] = Asb[r * AS_STR + kc + 4];
                af[mt][3] = Asb[(r + 8) * AS_STR + kc + 4];
            }
            #pragma unroll
            for (int nt = 0; nt < 4; nt++) {
                bf[nt][0] = Bsb[kc * BS_STR + bn + nt * 8];
                bf[nt][1] = Bsb[(kc + 4) * BS_STR + bn + nt * 8];
            }
            #pragma unroll
            for (int mt = 0; mt < 4; mt++)
                #pragma unroll
                for (int nt = 0; nt < 4; nt++) {
                    asm volatile(
                        "mma.sync.aligned.m16n8k8.row.col.f32.tf32.tf32.f32 "
                        "{%0,%1,%2,%3}, {%4,%5,%6,%7}, {%8,%9}, {%0,%1,%2,%3};\n"
                        : "+f"(acc[mt][nt][0]), "+f"(acc[mt][nt][1]),
                          "+f"(acc[mt][nt][2]), "+f"(acc[mt][nt][3])
                        : "r"(af[mt][0]), "r"(af[mt][1]), "r"(af[mt][2]), "r"(af[mt][3]),
                          "r"(bf[nt][0]), "r"(bf[nt][1]));
                }
        }

        if (!last) {
            store_s(buf ^ 1);
            __syncthreads();
            buf ^= 1;
        }
    }

    // epilogue: c0/c1 at (row, col), c2/c3 at (row+8, col); col = 2*(lane&3)
    const int r0 = block_row + warp_m + (lane >> 2);
    const int c0 = block_col + warp_n + (lane & 3) * 2;
    #pragma unroll
    for (int mt = 0; mt < 4; mt++) {
        #pragma unroll
        for (int hh = 0; hh < 2; hh++) {
            const int row = r0 + mt * 16 + hh * 8;
            if (row >= M) continue;
            #pragma unroll
            for (int nt = 0; nt < 4; nt++) {
                const int col = c0 + nt * 8;
                float2 d;
                d.x = acc[mt][nt][hh * 2 + 0] + bias[col + 0];
                d.y = acc[mt][nt][hh * 2 + 1] + bias[col + 1];
                if (add) {
                    const float2 ad = *(const float2*)&add[(size_t)row * N + col];
                    d.x += ad.x; d.y += ad.y;
                }
                *(float2*)&C[(size_t)row * N + col] = d;
            }
        }
    }
}

// ---------------------------------------------------------------------------
// Deformable sampling + warp softmax. One warp per (query, head).
// ---------------------------------------------------------------------------
__global__ void sampler_kernel(const float* __restrict__ refp)
{
    const int q    = blockIdx.x;
    const int h    = threadIdx.x >> 5;
    const int lane = threadIdx.x & 31;

    // ---- per-lane sample s = lane: coords + softmax weight ----
    const int s = lane;
    const int l = s >> 3;
    const int p = s & 7;
    const int z = p & 3;

    const float ox = g_off[(size_t)q * 512 + h * 64 + s * 2 + 0];
    const float oy = g_off[(size_t)q * 512 + h * 64 + s * 2 + 1];
    const float rx = refp[(size_t)q * 8 + z * 2 + 0];
    const float ry = refp[(size_t)q * 8 + z * 2 + 1];
    // (ref + off/W)*W - 0.5 == ref*W + off - 0.5
    const float x = rx * (float)c_W[l] + ox - 0.5f;
    const float y = ry * (float)c_H[l] + oy - 0.5f;

    float logit = g_logits[(size_t)q * 256 + h * 32 + s];
    float m = logit;
    #pragma unroll
    for (int o = 16; o > 0; o >>= 1) m = fmaxf(m, __shfl_xor_sync(0xffffffffu, m, o));
    float e = __expf(logit - m);
    float sum = e;
    #pragma unroll
    for (int o = 16; o > 0; o >>= 1) sum += __shfl_xor_sync(0xffffffffu, sum, o);
    const float w = e / sum;

    // ---- accumulation ----
    const int g  = lane >> 3;          // sample group 0..3
    const int cl = (lane & 7) * 4;     // channel quad 0,4,...,28
    float4 acc = make_float4(0.f, 0.f, 0.f, 0.f);
    const size_t coff = (size_t)h * DHEAD + cl;

    #pragma unroll
    for (int it = 0; it < 8; it++) {
        const int s2 = it * 4 + g;
        const float xs = __shfl_sync(0xffffffffu, x, s2);
        const float ys = __shfl_sync(0xffffffffu, y, s2);
        const float ws = __shfl_sync(0xffffffffu, w, s2);
        const int   ls = s2 >> 3;
        const int   W2 = c_W[ls], H2 = c_H[ls];
        const int   base = c_start[ls];

        const float x0f = floorf(xs), y0f = floorf(ys);
        const int   x0 = (int)x0f,    y0 = (int)y0f;
        const float lx = xs - x0f,    ly = ys - y0f;

        const float w00 = ws * (1.f - lx) * (1.f - ly);
        const float w10 = ws * lx * (1.f - ly);
        const float w01 = ws * (1.f - lx) * ly;
        const float w11 = ws * lx * ly;

        const bool vx0 = (x0 >= 0) & (x0 < W2);
        const bool vx1 = (x0 + 1 >= 0) & (x0 + 1 < W2);
        const bool vy0 = (y0 >= 0) & (y0 < H2);
        const bool vy1 = (y0 + 1 >= 0) & (y0 + 1 < H2);

        const float* row0 = g_v + ((size_t)(base + y0 * W2 + x0) * EMB + coff);
        const float* row1 = row0 + (size_t)W2 * EMB;

        if (vy0) {
            if (vx0) {
                const float4 t = *(const float4*)row0;
                acc.x = fmaf(w00, t.x, acc.x); acc.y = fmaf(w00, t.y, acc.y);
                acc.z = fmaf(w00, t.z, acc.z); acc.w = fmaf(w00, t.w, acc.w);
            }
            if (vx1) {
                const float4 t = *(const float4*)(row0 + EMB);
                acc.x = fmaf(w10, t.x, acc.x); acc.y = fmaf(w10, t.y, acc.y);
                acc.z = fmaf(w10, t.z, acc.z); acc.w = fmaf(w10, t.w, acc.w);
            }
        }
        if (vy1) {
            if (vx0) {
                const float4 t = *(const float4*)row1;
                acc.x = fmaf(w01, t.x, acc.x); acc.y = fmaf(w01, t.y, acc.y);
                acc.z = fmaf(w01, t.z, acc.z); acc.w = fmaf(w01, t.w, acc.w);
            }
            if (vx1) {
                const float4 t = *(const float4*)(row1 + EMB);
                acc.x = fmaf(w11, t.x, acc.x); acc.y = fmaf(w11, t.y, acc.y);
                acc.z = fmaf(w11, t.z, acc.z); acc.w = fmaf(w11, t.w, acc.w);
            }
        }
    }

    // reduce across the 4 sample-groups (lanes stride 8)
    #pragma unroll
    for (int o = 8; o < 32; o <<= 1) {
        acc.x += __shfl_xor_sync(0xffffffffu, acc.x, o);
        acc.y += __shfl_xor_sync(0xffffffffu, acc.y, o);
        acc.z += __shfl_xor_sync(0xffffffffu, acc.z, o);
        acc.w += __shfl_xor_sync(0xffffffffu, acc.w, o);
    }
    if (lane < 8)
        *(float4*)&g_samp[(size_t)q * EMB + h * DHEAD + cl] = acc;
}

// ---------------------------------------------------------------------------
// Launch
// ---------------------------------------------------------------------------
static float* sym_addr(const void* symbol) {
    void* p = nullptr;
    cudaGetSymbolAddress(&p, symbol);
    return (float*)p;
}

extern "C" void kernel_launch(void* const* d_in, const int* in_sizes, int n_in,
                              void* d_out, int out_size)
{
    const float* query  = (const float*)d_in[0];
    const float* value  = (const float*)d_in[1];
    const float* qpos   = (const float*)d_in[2];
    const float* refp   = (const float*)d_in[3];
    // d_in[4] spatial_shapes: static, baked into constants
    const float* W_off  = (const float*)d_in[5];
    const float* b_off  = (const float*)d_in[6];
    const float* W_attn = (const float*)d_in[7];
    const float* b_attn = (const float*)d_in[8];
    const float* W_val  = (const float*)d_in[9];
    const float* b_val  = (const float*)d_in[10];
    const float* W_out  = (const float*)d_in[11];
    const float* b_out  = (const float*)d_in[12];
    float* out = (float*)d_out;

    float* vb    = sym_addr(g_v);
    float* offb  = sym_addr(g_off);
    float* logb  = sym_addr(g_logits);
    float* sampb = sym_addr(g_samp);

    // 1. v = value @ W_val + b_val   [19560 x 256]
    {
        dim3 grid(EMB / 128, (NV + 127) / 128);
        gemm_tf32_kernel<<<grid, 256>>>(value, nullptr, W_val, b_val, nullptr, vb, NV, EMB, EMB);
    }
    // 2. off = (query+qpos) @ W_off + b_off   [10000 x 512]  (q-add fused)
    {
        dim3 grid(512 / 128, (NQ + 127) / 128);
        gemm_tf32_kernel<<<grid, 256>>>(query, qpos, W_off, b_off, nullptr, offb, NQ, 512, EMB);
    }
    // 3. logits = (query+qpos) @ W_attn + b_attn  [10000 x 256]
    {
        dim3 grid(256 / 128, (NQ + 127) / 128);
        gemm_tf32_kernel<<<grid, 256>>>(query, qpos, W_attn, b_attn, nullptr, logb, NQ, 256, EMB);
    }
    // 4. deformable sampling (softmax fused in-warp)
    sampler_kernel<<<NQ, 256>>>(refp);

    // 5. out = samp @ W_out + b_out + query (residual)
    {
        dim3 grid(EMB / 128, (NQ + 127) / 128);
        gemm_tf32_kernel<<<grid, 256>>>(sampb, nullptr, W_out, b_out, query, out, NQ, EMB, EMB);
    }
}

// round 7
// speedup vs baseline: 2.5924x; 1.9076x over previous
#include <cuda_runtime.h>
#include <cuda_fp16.h>
#include <cstdint>

// Problem constants (match reference setup_inputs)
#define NQ    10000
#define NV    19560
#define EMB   256
#define HEADS 8
#define DHEAD 32

__device__ __constant__ int c_H[4]     = {92, 46, 23, 12};
__device__ __constant__ int c_W[4]     = {160, 80, 40, 20};
__device__ __constant__ int c_start[4] = {0, 14720, 18400, 19320};

// Scratch (static __device__ arrays — no allocation allowed)
__device__ __align__(16) __half g_vh[(size_t)NV * EMB];   // projected values, fp16
__device__ __align__(16) float  g_off[NQ * 512];          // sampling offsets
__device__ __align__(16) float  g_logits[NQ * 256];       // attention logits
__device__ __align__(16) float  g_samp[NQ * EMB];         // aggregated sampled values

__device__ __forceinline__ uint32_t f2tf32(float x) {
    uint32_t r;
    asm("cvt.rna.tf32.f32 %0, %1;" : "=r"(r) : "f"(x));
    return r;
}

// ---------------------------------------------------------------------------
// Multi-segment TF32 tensor-core GEMM.
// Each segment: C[M,N] = (A (+A2))[M,256] @ B[256,N] + bias[N] (+ add[M,N])
// Output to float (Cf) or fp16 (Ch). Block 128x128, BK=16, 256 thr = 8 warps,
// warp tile 64x32, mma.m16n8k8.tf32, double-buffered smem.
// Requirements: K = 256, N % 128 == 0.
// ---------------------------------------------------------------------------
#define AS_STR 20
#define BS_STR 132
#define GK     256

struct GemmSeg {
    const float* A;
    const float* A2;
    const float* B;
    const float* bias;
    const float* add;
    float*       Cf;
    __half*      Ch;
    int M, N, nbx, blk0;   // nbx = N/128, blk0 = first linear block id
};
struct GemmArgs { GemmSeg s[3]; };

__global__ void __launch_bounds__(256)
gemm_tf32_multi(GemmArgs args)
{
    __shared__ uint32_t As[2][128 * AS_STR];
    __shared__ uint32_t Bs[2][16 * BS_STR];

    const int bi = blockIdx.x;
    const GemmSeg* sp = &args.s[0];
    if (bi >= args.s[2].blk0)      sp = &args.s[2];
    else if (bi >= args.s[1].blk0) sp = &args.s[1];
    const int local = bi - sp->blk0;
    const int M = sp->M, N = sp->N;
    const int block_row = (local / sp->nbx) * 128;
    const int block_col = (local % sp->nbx) * 128;

    const int tid  = threadIdx.x;
    const int wid  = tid >> 5;
    const int lane = tid & 31;
    const int warp_m = (wid >> 2) * 64;
    const int warp_n = (wid & 3) * 32;

    const int am  = tid >> 1;
    const int akq = (tid & 1) * 8;
    const int bk  = tid >> 4;
    const int bc  = (tid & 15) * 4;

    const int arow = min(block_row + am, M - 1);
    const float* Ap  = sp->A + (size_t)arow * GK + akq;
    const float* A2p = sp->A2 ? sp->A2 + (size_t)arow * GK + akq : nullptr;
    const float* Bp  = sp->B + (size_t)bk * N + block_col + bc;

    float acc[4][4][4] = {};
    float pa[8];
    float4 pb0, pb1;

    auto load_g = [&](int k0) {
        float4 v0 = *(const float4*)&Ap[k0];
        float4 v1 = *(const float4*)&Ap[k0 + 4];
        if (A2p) {
            float4 q0 = *(const float4*)&A2p[k0];
            float4 q1 = *(const float4*)&A2p[k0 + 4];
            v0.x += q0.x; v0.y += q0.y; v0.z += q0.z; v0.w += q0.w;
            v1.x += q1.x; v1.y += q1.y; v1.z += q1.z; v1.w += q1.w;
        }
        pa[0] = v0.x; pa[1] = v0.y; pa[2] = v0.z; pa[3] = v0.w;
        pa[4] = v1.x; pa[5] = v1.y; pa[6] = v1.z; pa[7] = v1.w;
        pb0 = *(const float4*)&Bp[(size_t)k0 * N];
        pb1 = *(const float4*)&Bp[(size_t)k0 * N + 64];
    };
    auto store_s = [&](int b) {
        #pragma unroll
        for (int i = 0; i < 8; i++)
            As[b][am * AS_STR + akq + i] = f2tf32(pa[i]);
        uint4 u0, u1;
        u0.x = f2tf32(pb0.x); u0.y = f2tf32(pb0.y); u0.z = f2tf32(pb0.z); u0.w = f2tf32(pb0.w);
        u1.x = f2tf32(pb1.x); u1.y = f2tf32(pb1.y); u1.z = f2tf32(pb1.z); u1.w = f2tf32(pb1.w);
        *(uint4*)&Bs[b][bk * BS_STR + bc]      = u0;
        *(uint4*)&Bs[b][bk * BS_STR + bc + 64] = u1;
    };

    load_g(0);
    store_s(0);
    __syncthreads();

    int buf = 0;
    for (int k0 = 0; k0 < GK; k0 += 16) {
        const bool last = (k0 + 16 >= GK);
        if (!last) load_g(k0 + 16);

        const uint32_t* Asb = As[buf];
        const uint32_t* Bsb = Bs[buf];
        const int ar = warp_m + (lane >> 2);
        const int bn = warp_n + (lane >> 2);

        #pragma unroll
        for (int ks = 0; ks < 2; ks++) {
            const int kc = ks * 8 + (lane & 3);
            uint32_t af[4][4], bf[4][2];
            #pragma unroll
            for (int mt = 0; mt < 4; mt++) {
                const int r = ar + mt * 16;
                af[mt][0] = Asb[r * AS_STR + kc];
                af[mt][1] = Asb[(r + 8) * AS_STR + kc];
                af[mt][2] = Asb[r * AS_STR + kc + 4];
                af[mt][3] = Asb[(r + 8) * AS_STR + kc + 4];
            }
            #pragma unroll
            for (int nt = 0; nt < 4; nt++) {
                bf[nt][0] = Bsb[kc * BS_STR + bn + nt * 8];
                bf[nt][1] = Bsb[(kc + 4) * BS_STR + bn + nt * 8];
            }
            #pragma unroll
            for (int mt = 0; mt < 4; mt++)
                #pragma unroll
                for (int nt = 0; nt < 4; nt++) {
                    asm volatile(
                        "mma.sync.aligned.m16n8k8.row.col.f32.tf32.tf32.f32 "
                        "{%0,%1,%2,%3}, {%4,%5,%6,%7}, {%8,%9}, {%0,%1,%2,%3};\n"
                        : "+f"(acc[mt][nt][0]), "+f"(acc[mt][nt][1]),
                          "+f"(acc[mt][nt][2]), "+f"(acc[mt][nt][3])
                        : "r"(af[mt][0]), "r"(af[mt][1]), "r"(af[mt][2]), "r"(af[mt][3]),
                          "r"(bf[nt][0]), "r"(bf[nt][1]));
                }
        }

        if (!last) {
            store_s(buf ^ 1);
            __syncthreads();
            buf ^= 1;
        }
    }

    // epilogue: c0/c1 at (row, col), c2/c3 at (row+8, col); col = 2*(lane&3)
    const int r0 = block_row + warp_m + (lane >> 2);
    const int c0 = block_col + warp_n + (lane & 3) * 2;
    const float* bias = sp->bias;
    #pragma unroll
    for (int mt = 0; mt < 4; mt++) {
        #pragma unroll
        for (int hh = 0; hh < 2; hh++) {
            const int row = r0 + mt * 16 + hh * 8;
            if (row >= M) continue;
            #pragma unroll
            for (int nt = 0; nt < 4; nt++) {
                const int col = c0 + nt * 8;
                float2 d;
                d.x = acc[mt][nt][hh * 2 + 0] + bias[col + 0];
                d.y = acc[mt][nt][hh * 2 + 1] + bias[col + 1];
                if (sp->add) {
                    const float2 ad = *(const float2*)&sp->add[(size_t)row * N + col];
                    d.x += ad.x; d.y += ad.y;
                }
                if (sp->Ch) {
                    *(__half2*)&sp->Ch[(size_t)row * N + col] = __floats2half2_rn(d.x, d.y);
                } else {
                    *(float2*)&sp->Cf[(size_t)row * N + col] = d;
                }
            }
        }
    }
}

// ---------------------------------------------------------------------------
// Deformable sampling + warp softmax. One warp per (query, head).
// fp16 value gathers (uint2 = 4 channels).
// ---------------------------------------------------------------------------
__global__ void sampler_kernel(const float* __restrict__ refp)
{
    const int q    = blockIdx.x;
    const int h    = threadIdx.x >> 5;
    const int lane = threadIdx.x & 31;

    // ---- per-lane sample s = lane: coords + softmax weight ----
    const int s = lane;
    const int l = s >> 3;
    const int p = s & 7;
    const int z = p & 3;

    const float ox = g_off[(size_t)q * 512 + h * 64 + s * 2 + 0];
    const float oy = g_off[(size_t)q * 512 + h * 64 + s * 2 + 1];
    const float rx = refp[(size_t)q * 8 + z * 2 + 0];
    const float ry = refp[(size_t)q * 8 + z * 2 + 1];
    // (ref + off/W)*W - 0.5 == ref*W + off - 0.5
    const float x = rx * (float)c_W[l] + ox - 0.5f;
    const float y = ry * (float)c_H[l] + oy - 0.5f;

    float logit = g_logits[(size_t)q * 256 + h * 32 + s];
    float m = logit;
    #pragma unroll
    for (int o = 16; o > 0; o >>= 1) m = fmaxf(m, __shfl_xor_sync(0xffffffffu, m, o));
    float e = __expf(logit - m);
    float sum = e;
    #pragma unroll
    for (int o = 16; o > 0; o >>= 1) sum += __shfl_xor_sync(0xffffffffu, sum, o);
    const float w = e / sum;

    // ---- accumulation: group g owns samples it*4+g, channel quad cl ----
    const int g  = lane >> 3;
    const int cl = (lane & 7) * 4;
    float4 acc = make_float4(0.f, 0.f, 0.f, 0.f);
    const size_t coff = (size_t)h * DHEAD + cl;

    #pragma unroll
    for (int it = 0; it < 8; it++) {
        const int s2 = it * 4 + g;
        const float xs = __shfl_sync(0xffffffffu, x, s2);
        const float ys = __shfl_sync(0xffffffffu, y, s2);
        const float ws = __shfl_sync(0xffffffffu, w, s2);
        const int   ls = s2 >> 3;
        const int   W2 = c_W[ls], H2 = c_H[ls];
        const int   base = c_start[ls];

        const float x0f = floorf(xs), y0f = floorf(ys);
        const int   x0 = (int)x0f,    y0 = (int)y0f;
        const float lx = xs - x0f,    ly = ys - y0f;

        const float w00 = ws * (1.f - lx) * (1.f - ly);
        const float w10 = ws * lx * (1.f - ly);
        const float w01 = ws * (1.f - lx) * ly;
        const float w11 = ws * lx * ly;

        const bool vx0 = (x0 >= 0) & (x0 < W2);
        const bool vx1 = (x0 + 1 >= 0) & (x0 + 1 < W2);
        const bool vy0 = (y0 >= 0) & (y0 < H2);
        const bool vy1 = (y0 + 1 >= 0) & (y0 + 1 < H2);

        const __half* row0 = g_vh + ((size_t)(base + y0 * W2 + x0) * EMB + coff);
        const __half* row1 = row0 + (size_t)W2 * EMB;

        #define CORNER(ptr, wgt) do {                                          \
            const uint2 u = *(const uint2*)(ptr);                              \
            const float2 f0 = __half22float2(*(const __half2*)&u.x);           \
            const float2 f1 = __half22float2(*(const __half2*)&u.y);           \
            acc.x = fmaf(wgt, f0.x, acc.x); acc.y = fmaf(wgt, f0.y, acc.y);    \
            acc.z = fmaf(wgt, f1.x, acc.z); acc.w = fmaf(wgt, f1.y, acc.w);    \
        } while (0)

        if (vy0) {
            if (vx0) CORNER(row0, w00);
            if (vx1) CORNER(row0 + EMB, w10);
        }
        if (vy1) {
            if (vx0) CORNER(row1, w01);
            if (vx1) CORNER(row1 + EMB, w11);
        }
        #undef CORNER
    }

    // reduce across the 4 sample-groups (lanes stride 8)
    #pragma unroll
    for (int o = 8; o < 32; o <<= 1) {
        acc.x += __shfl_xor_sync(0xffffffffu, acc.x, o);
        acc.y += __shfl_xor_sync(0xffffffffu, acc.y, o);
        acc.z += __shfl_xor_sync(0xffffffffu, acc.z, o);
        acc.w += __shfl_xor_sync(0xffffffffu, acc.w, o);
    }
    if (lane < 8)
        *(float4*)&g_samp[(size_t)q * EMB + h * DHEAD + cl] = acc;
}

// ---------------------------------------------------------------------------
// Launch
// ---------------------------------------------------------------------------
static void* sym_addr(const void* symbol) {
    void* p = nullptr;
    cudaGetSymbolAddress(&p, symbol);
    return p;
}

extern "C" void kernel_launch(void* const* d_in, const int* in_sizes, int n_in,
                              void* d_out, int out_size)
{
    const float* query  = (const float*)d_in[0];
    const float* value  = (const float*)d_in[1];
    const float* qpos   = (const float*)d_in[2];
    const float* refp   = (const float*)d_in[3];
    // d_in[4] spatial_shapes: static, baked into constants
    const float* W_off  = (const float*)d_in[5];
    const float* b_off  = (const float*)d_in[6];
    const float* W_attn = (const float*)d_in[7];
    const float* b_attn = (const float*)d_in[8];
    const float* W_val  = (const float*)d_in[9];
    const float* b_val  = (const float*)d_in[10];
    const float* W_out  = (const float*)d_in[11];
    const float* b_out  = (const float*)d_in[12];
    float* out = (float*)d_out;

    __half* vhb  = (__half*)sym_addr(g_vh);
    float*  offb = (float*)sym_addr(g_off);
    float*  logb = (float*)sym_addr(g_logits);
    float*  sampb= (float*)sym_addr(g_samp);

    // block counts: v = 2*153=306, off = 4*79=316, logits = 2*79=158
    const int nbv = ((NV + 127) / 128) * 2;
    const int nbo = ((NQ + 127) / 128) * 4;
    const int nbl = ((NQ + 127) / 128) * 2;

    // --- merged front GEMMs: v-proj (fp16 out), off-proj, logits ---
    {
        GemmArgs ga;
        ga.s[0] = {value, nullptr, W_val,  b_val,  nullptr, nullptr, vhb,
                   NV, 256, 2, 0};
        ga.s[1] = {query, qpos,    W_off,  b_off,  nullptr, offb, nullptr,
                   NQ, 512, 4, nbv};
        ga.s[2] = {query, qpos,    W_attn, b_attn, nullptr, logb, nullptr,
                   NQ, 256, 2, nbv + nbo};
        gemm_tf32_multi<<<nbv + nbo + nbl, 256>>>(ga);
    }

    // --- deformable sampling (softmax fused in-warp) ---
    sampler_kernel<<<NQ, 256>>>(refp);

    // --- out = samp @ W_out + b_out + query (residual) ---
    {
        GemmArgs ga;
        ga.s[0] = {sampb, nullptr, W_out, b_out, query, out, nullptr,
                   NQ, 256, 2, 0};
        ga.s[1] = ga.s[0]; ga.s[1].blk0 = 1 << 30;
        ga.s[2] = ga.s[0]; ga.s[2].blk0 = 1 << 30;
        gemm_tf32_multi<<<nbl, 256>>>(ga);
    }
}

// round 8
// speedup vs baseline: 2.9652x; 1.1438x over previous
#include <cuda_runtime.h>
#include <cuda_fp16.h>
#include <cstdint>

// Problem constants (match reference setup_inputs)
#define NQ    10000
#define NV    19560
#define EMB   256
#define HEADS 8
#define DHEAD 32

__device__ __constant__ int c_H[4]     = {92, 46, 23, 12};
__device__ __constant__ int c_W[4]     = {160, 80, 40, 20};
__device__ __constant__ int c_start[4] = {0, 14720, 18400, 19320};

// Scratch (static __device__ arrays — no allocation allowed)
__device__ __align__(16) float  g_q[NQ * EMB];            // query + query_pos
__device__ __align__(16) __half g_vh[(size_t)NV * EMB];   // projected values, fp16
__device__ __align__(16) float  g_off[NQ * 512];          // sampling offsets
__device__ __align__(16) float  g_logits[NQ * 256];       // attention logits
__device__ __align__(16) float  g_samp[NQ * EMB];         // aggregated sampled values

// ---------------------------------------------------------------------------
// q = query + query_pos
// ---------------------------------------------------------------------------
__global__ void addq_kernel(const float* __restrict__ a, const float* __restrict__ b) {
    int i = blockIdx.x * blockDim.x + threadIdx.x;
    if (i < NQ * 64) {
        float4 x = *(const float4*)&a[i * 4];
        float4 y = *(const float4*)&b[i * 4];
        x.x += y.x; x.y += y.y; x.z += y.z; x.w += y.w;
        *(float4*)&g_q[i * 4] = x;
    }
}

// ---------------------------------------------------------------------------
// Multi-segment TF32 tensor-core GEMM, cp.async 3-stage pipeline.
// Each segment: C[M,N] = A[M,256] @ B[256,N] + bias[N] (+ add[M,N])
// Output float (Cf) or fp16 (Ch). Block 128x128, BK=32, 256 thr = 8 warps,
// warp tile 64x32, mma.m16n8k8.tf32 (raw fp32 bits = tf32 truncation).
// K = 256, N % 128 == 0 required.
// ---------------------------------------------------------------------------
#define GK      256
#define NIT     8            // GK / 32
#define NSTAGE  3
#define AS_F    36           // A smem row stride (floats), conflict-free
#define BS_F    136          // B smem row stride (floats), conflict-free
#define A_STG_F (128 * AS_F)
#define B_STG_F (32 * BS_F)
#define STG_F   (A_STG_F + B_STG_F)
#define SMEM_BYTES (NSTAGE * STG_F * 4)

struct GemmSeg {
    const float* A;
    const float* B;
    const float* bias;
    const float* add;
    float*       Cf;
    __half*      Ch;
    int M, N, nbx, blk0;
};
struct GemmArgs { GemmSeg s[3]; };

__device__ __forceinline__ void cp16(uint32_t dst, const float* src) {
    asm volatile("cp.async.cg.shared.global [%0], [%1], 16;\n"
                 :: "r"(dst), "l"(src) : "memory");
}
__device__ __forceinline__ void cp_commit() {
    asm volatile("cp.async.commit_group;\n" ::: "memory");
}
template <int N> __device__ __forceinline__ void cp_wait() {
    asm volatile("cp.async.wait_group %0;\n" :: "n"(N) : "memory");
}
__device__ __forceinline__ uint32_t smem_u32(const void* p) {
    uint32_t a;
    asm("{ .reg .u64 t; cvta.to.shared.u64 t, %1; cvt.u32.u64 %0, t; }" : "=r"(a) : "l"(p));
    return a;
}

__global__ void __launch_bounds__(256)
gemm_tf32_multi(GemmArgs args)
{
    extern __shared__ float smem[];
    const uint32_t smb = smem_u32(smem);

    const int bi = blockIdx.x;
    const GemmSeg* sp = &args.s[0];
    if (bi >= args.s[2].blk0)      sp = &args.s[2];
    else if (bi >= args.s[1].blk0) sp = &args.s[1];
    const int local = bi - sp->blk0;
    const int M = sp->M, N = sp->N;
    const int block_row = (local / sp->nbx) * 128;
    const int block_col = (local % sp->nbx) * 128;

    const int tid  = threadIdx.x;
    const int wid  = tid >> 5;
    const int lane = tid & 31;
    const int warp_m = (wid >> 2) * 64;
    const int warp_n = (wid & 3) * 32;

    // ---- async load mappings ----
    const int la_row  = tid >> 1;             // A tile row 0..127
    const int la_half = tid & 1;              // floats 0-15 / 16-31
    const int arow = min(block_row + la_row, M - 1);
    const float* Asrc = sp->A + (size_t)arow * GK + la_half * 16;
    const uint32_t Adst = smb + (la_row * AS_F + la_half * 16) * 4;

    const int lb_row = tid >> 3;              // B k-row 0..31
    const int lb_c   = tid & 7;               // 16B chunk within row
    const float* Bsrc = sp->B + (size_t)lb_row * N + block_col + lb_c * 4;
    const uint32_t Bdst = smb + (A_STG_F + lb_row * BS_F + lb_c * 4) * 4;

    auto load_stage = [&](int s, int k0) {
        const uint32_t sa = Adst + s * (STG_F * 4);
        const float* asrc = Asrc + k0;
        #pragma unroll
        for (int c = 0; c < 4; c++)
            cp16(sa + c * 16, asrc + c * 4);
        const uint32_t sbda = Bdst + s * (STG_F * 4);
        const float* bsrc = Bsrc + (size_t)k0 * N;
        #pragma unroll
        for (int i = 0; i < 4; i++)
            cp16(sbda + i * 128, bsrc + i * 32);
    };

    // ---- fragment address bases ----
    const int j  = lane >> 3;                 // ldmatrix matrix id
    const int rr = lane & 7;
    const uint32_t a_frag0 = smb + ((warp_m + (j & 1) * 8 + rr) * AS_F + (j >> 1) * 4) * 4;
    const int kc_l = lane & 3;
    const int bn   = warp_n + (lane >> 2);

    float acc[4][4][4] = {};

    load_stage(0, 0);  cp_commit();
    load_stage(1, 32); cp_commit();

    for (int i = 0; i < NIT; i++) {
        if (i + 2 < NIT) {
            load_stage((i + 2) % NSTAGE, (i + 2) * 32);
            cp_commit();
            cp_wait<2>();
        } else if (i == NIT - 2) {
            cp_wait<1>();
        } else {
            cp_wait<0>();
        }
        __syncthreads();

        const int s = i % NSTAGE;
        const uint32_t a_st = a_frag0 + s * (STG_F * 4);
        const float* Bsb = smem + s * STG_F + A_STG_F;

        #pragma unroll
        for (int ks = 0; ks < 4; ks++) {
            uint32_t af[4][4], bf[4][2];
            #pragma unroll
            for (int mt = 0; mt < 4; mt++) {
                const uint32_t ad = a_st + (mt * 16 * AS_F + ks * 8) * 4;
                asm volatile("ldmatrix.sync.aligned.m8n8.x4.shared.b16 "
                             "{%0,%1,%2,%3}, [%4];\n"
                             : "=r"(af[mt][0]), "=r"(af[mt][1]),
                               "=r"(af[mt][2]), "=r"(af[mt][3])
                             : "r"(ad));
            }
            const int kc = ks * 8 + kc_l;
            #pragma unroll
            for (int nt = 0; nt < 4; nt++) {
                bf[nt][0] = __float_as_uint(Bsb[kc * BS_F + bn + nt * 8]);
                bf[nt][1] = __float_as_uint(Bsb[(kc + 4) * BS_F + bn + nt * 8]);
            }
            #pragma unroll
            for (int mt = 0; mt < 4; mt++)
                #pragma unroll
                for (int nt = 0; nt < 4; nt++) {
                    asm volatile(
                        "mma.sync.aligned.m16n8k8.row.col.f32.tf32.tf32.f32 "
                        "{%0,%1,%2,%3}, {%4,%5,%6,%7}, {%8,%9}, {%0,%1,%2,%3};\n"
                        : "+f"(acc[mt][nt][0]), "+f"(acc[mt][nt][1]),
                          "+f"(acc[mt][nt][2]), "+f"(acc[mt][nt][3])
                        : "r"(af[mt][0]), "r"(af[mt][1]), "r"(af[mt][2]), "r"(af[mt][3]),
                          "r"(bf[nt][0]), "r"(bf[nt][1]));
                }
        }
        __syncthreads();
    }

    // epilogue: c0/c1 at (row, col), c2/c3 at (row+8, col); col = 2*(lane&3)
    const int r0 = block_row + warp_m + (lane >> 2);
    const int c0 = block_col + warp_n + (lane & 3) * 2;
    const float* bias = sp->bias;
    #pragma unroll
    for (int mt = 0; mt < 4; mt++) {
        #pragma unroll
        for (int hh = 0; hh < 2; hh++) {
            const int row = r0 + mt * 16 + hh * 8;
            if (row >= M) continue;
            #pragma unroll
            for (int nt = 0; nt < 4; nt++) {
                const int col = c0 + nt * 8;
                float2 d;
                d.x = acc[mt][nt][hh * 2 + 0] + bias[col + 0];
                d.y = acc[mt][nt][hh * 2 + 1] + bias[col + 1];
                if (sp->add) {
                    const float2 ad = *(const float2*)&sp->add[(size_t)row * N + col];
                    d.x += ad.x; d.y += ad.y;
                }
                if (sp->Ch) {
                    *(__half2*)&sp->Ch[(size_t)row * N + col] = __floats2half2_rn(d.x, d.y);
                } else {
                    *(float2*)&sp->Cf[(size_t)row * N + col] = d;
                }
            }
        }
    }
}

// ---------------------------------------------------------------------------
// Deformable sampling + warp softmax. One warp per (query, head).
// fp16 value gathers (uint2 = 4 channels).
// ---------------------------------------------------------------------------
__global__ void sampler_kernel(const float* __restrict__ refp)
{
    const int q    = blockIdx.x;
    const int h    = threadIdx.x >> 5;
    const int lane = threadIdx.x & 31;

    const int s = lane;
    const int l = s >> 3;
    const int p = s & 7;
    const int z = p & 3;

    const float ox = g_off[(size_t)q * 512 + h * 64 + s * 2 + 0];
    const float oy = g_off[(size_t)q * 512 + h * 64 + s * 2 + 1];
    const float rx = refp[(size_t)q * 8 + z * 2 + 0];
    const float ry = refp[(size_t)q * 8 + z * 2 + 1];
    const float x = rx * (float)c_W[l] + ox - 0.5f;
    const float y = ry * (float)c_H[l] + oy - 0.5f;

    float logit = g_logits[(size_t)q * 256 + h * 32 + s];
    float m = logit;
    #pragma unroll
    for (int o = 16; o > 0; o >>= 1) m = fmaxf(m, __shfl_xor_sync(0xffffffffu, m, o));
    float e = __expf(logit - m);
    float sum = e;
    #pragma unroll
    for (int o = 16; o > 0; o >>= 1) sum += __shfl_xor_sync(0xffffffffu, sum, o);
    const float w = e / sum;

    const int g  = lane >> 3;
    const int cl = (lane & 7) * 4;
    float4 acc = make_float4(0.f, 0.f, 0.f, 0.f);
    const size_t coff = (size_t)h * DHEAD + cl;

    #pragma unroll
    for (int it = 0; it < 8; it++) {
        const int s2 = it * 4 + g;
        const float xs = __shfl_sync(0xffffffffu, x, s2);
        const float ys = __shfl_sync(0xffffffffu, y, s2);
        const float ws = __shfl_sync(0xffffffffu, w, s2);
        const int   ls = s2 >> 3;
        const int   W2 = c_W[ls], H2 = c_H[ls];
        const int   base = c_start[ls];

        const float x0f = floorf(xs), y0f = floorf(ys);
        const int   x0 = (int)x0f,    y0 = (int)y0f;
        const float lx = xs - x0f,    ly = ys - y0f;

        const float w00 = ws * (1.f - lx) * (1.f - ly);
        const float w10 = ws * lx * (1.f - ly);
        const float w01 = ws * (1.f - lx) * ly;
        const float w11 = ws * lx * ly;

        const bool vx0 = (x0 >= 0) & (x0 < W2);
        const bool vx1 = (x0 + 1 >= 0) & (x0 + 1 < W2);
        const bool vy0 = (y0 >= 0) & (y0 < H2);
        const bool vy1 = (y0 + 1 >= 0) & (y0 + 1 < H2);

        const __half* row0 = g_vh + ((size_t)(base + y0 * W2 + x0) * EMB + coff);
        const __half* row1 = row0 + (size_t)W2 * EMB;

        #define CORNER(ptr, wgt) do {                                          \
            const uint2 u = *(const uint2*)(ptr);                              \
            const float2 f0 = __half22float2(*(const __half2*)&u.x);           \
            const float2 f1 = __half22float2(*(const __half2*)&u.y);           \
            acc.x = fmaf(wgt, f0.x, acc.x); acc.y = fmaf(wgt, f0.y, acc.y);    \
            acc.z = fmaf(wgt, f1.x, acc.z); acc.w = fmaf(wgt, f1.y, acc.w);    \
        } while (0)

        if (vy0) {
            if (vx0) CORNER(row0, w00);
            if (vx1) CORNER(row0 + EMB, w10);
        }
        if (vy1) {
            if (vx0) CORNER(row1, w01);
            if (vx1) CORNER(row1 + EMB, w11);
        }
        #undef CORNER
    }

    #pragma unroll
    for (int o = 8; o < 32; o <<= 1) {
        acc.x += __shfl_xor_sync(0xffffffffu, acc.x, o);
        acc.y += __shfl_xor_sync(0xffffffffu, acc.y, o);
        acc.z += __shfl_xor_sync(0xffffffffu, acc.z, o);
        acc.w += __shfl_xor_sync(0xffffffffu, acc.w, o);
    }
    if (lane < 8)
        *(float4*)&g_samp[(size_t)q * EMB + h * DHEAD + cl] = acc;
}

// ---------------------------------------------------------------------------
// Launch
// ---------------------------------------------------------------------------
static void* sym_addr(const void* symbol) {
    void* p = nullptr;
    cudaGetSymbolAddress(&p, symbol);
    return p;
}

extern "C" void kernel_launch(void* const* d_in, const int* in_sizes, int n_in,
                              void* d_out, int out_size)
{
    const float* query  = (const float*)d_in[0];
    const float* value  = (const float*)d_in[1];
    const float* qpos   = (const float*)d_in[2];
    const float* refp   = (const float*)d_in[3];
    // d_in[4] spatial_shapes: static, baked into constants
    const float* W_off  = (const float*)d_in[5];
    const float* b_off  = (const float*)d_in[6];
    const float* W_attn = (const float*)d_in[7];
    const float* b_attn = (const float*)d_in[8];
    const float* W_val  = (const float*)d_in[9];
    const float* b_val  = (const float*)d_in[10];
    const float* W_out  = (const float*)d_in[11];
    const float* b_out  = (const float*)d_in[12];
    float* out = (float*)d_out;

    float*  qb   = (float*)sym_addr(g_q);
    __half* vhb  = (__half*)sym_addr(g_vh);
    float*  offb = (float*)sym_addr(g_off);
    float*  logb = (float*)sym_addr(g_logits);
    float*  sampb= (float*)sym_addr(g_samp);

    static bool attr_set = false;
    if (!attr_set) {
        cudaFuncSetAttribute(gemm_tf32_multi,
                             cudaFuncAttributeMaxDynamicSharedMemorySize, SMEM_BYTES);
        attr_set = true;
    }

    // 0. q = query + query_pos
    addq_kernel<<<(NQ * 64 + 255) / 256, 256>>>(query, qpos);

    const int nbv = ((NV + 127) / 128) * 2;   // 306
    const int nbo = ((NQ + 127) / 128) * 4;   // 316
    const int nbl = ((NQ + 127) / 128) * 2;   // 158

    // 1. merged front GEMMs: v-proj (fp16 out), off-proj, logits
    {
        GemmArgs ga;
        ga.s[0] = {value, W_val,  b_val,  nullptr, nullptr, vhb, NV, 256, 2, 0};
        ga.s[1] = {qb,    W_off,  b_off,  nullptr, offb, nullptr, NQ, 512, 4, nbv};
        ga.s[2] = {qb,    W_attn, b_attn, nullptr, logb, nullptr, NQ, 256, 2, nbv + nbo};
        gemm_tf32_multi<<<nbv + nbo + nbl, 256, SMEM_BYTES>>>(ga);
    }

    // 2. deformable sampling (softmax fused in-warp)
    sampler_kernel<<<NQ, 256>>>(refp);

    // 3. out = samp @ W_out + b_out + query (residual)
    {
        GemmArgs ga;
        ga.s[0] = {sampb, W_out, b_out, query, out, nullptr, NQ, 256, 2, 0};
        ga.s[1] = ga.s[0]; ga.s[1].blk0 = 1 << 30;
        ga.s[2] = ga.s[0]; ga.s[2].blk0 = 1 << 30;
        gemm_tf32_multi<<<nbl, 256, SMEM_BYTES>>>(ga);
    }
}

// round 11
// speedup vs baseline: 3.6135x; 1.2186x over previous
#include <cuda_runtime.h>
#include <cuda_fp16.h>
#include <cstdint>

// Problem constants (match reference setup_inputs)
#define NQ    10000
#define NV    19560
#define EMB   256
#define HEADS 8
#define DHEAD 32

__device__ __constant__ int c_H[4]     = {92, 46, 23, 12};
__device__ __constant__ int c_W[4]     = {160, 80, 40, 20};
__device__ __constant__ int c_start[4] = {0, 14720, 18400, 19320};

// Scratch (static __device__ arrays — no allocation allowed)
__device__ __align__(16) __half g_qh[NQ * EMB];            // (query+qpos) fp16
__device__ __align__(16) __half g_valh[(size_t)NV * EMB];  // value fp16
__device__ __align__(16) __half g_vh[(size_t)NV * EMB];    // projected values fp16
__device__ __align__(16) __half g_samph[NQ * EMB];         // sampled values fp16
__device__ __align__(16) float  g_off[NQ * 512];           // sampling offsets
__device__ __align__(16) float  g_logits[NQ * 256];        // attention logits
// fp16 weights, [k=256][n] row-major
__device__ __align__(16) __half g_wvh[256 * 256];
__device__ __align__(16) __half g_woh[256 * 512];
__device__ __align__(16) __half g_wah[256 * 256];
__device__ __align__(16) __half g_wouth[256 * 256];

__device__ __forceinline__ void st_half4(__half* dst, float4 v) {
    __half2 h0 = __floats2half2_rn(v.x, v.y);
    __half2 h1 = __floats2half2_rn(v.z, v.w);
    uint2 u;
    u.x = *(uint32_t*)&h0;
    u.y = *(uint32_t*)&h1;
    *(uint2*)dst = u;
}

// ---------------------------------------------------------------------------
// One prep kernel: value->fp16, q=query+qpos->fp16, 4 weights->fp16
// Each thread handles 4 floats.
// ---------------------------------------------------------------------------
#define NV4 (NV * 64)
#define NQ4 (NQ * 64)
#define WV4 16384      /* 256*256/4 */
#define WO4 32768      /* 256*512/4 */
#define PREP_TOTAL (NV4 + NQ4 + WV4 + WO4 + WV4 + WV4)

__global__ void prep_kernel(const float* __restrict__ value,
                            const float* __restrict__ query,
                            const float* __restrict__ qpos,
                            const float* __restrict__ Wval,
                            const float* __restrict__ Woff,
                            const float* __restrict__ Wattn,
                            const float* __restrict__ Wout)
{
    int i = blockIdx.x * blockDim.x + threadIdx.x;
    if (i < NV4) {
        st_half4(&g_valh[(size_t)i * 4], *(const float4*)&value[(size_t)i * 4]);
        return;
    }
    i -= NV4;
    if (i < NQ4) {
        float4 a = *(const float4*)&query[(size_t)i * 4];
        float4 b = *(const float4*)&qpos[(size_t)i * 4];
        a.x += b.x; a.y += b.y; a.z += b.z; a.w += b.w;
        st_half4(&g_qh[(size_t)i * 4], a);
        return;
    }
    i -= NQ4;
    if (i < WV4) { st_half4(&g_wvh[i * 4], *(const float4*)&Wval[i * 4]); return; }
    i -= WV4;
    if (i < WO4) { st_half4(&g_woh[i * 4], *(const float4*)&Woff[i * 4]); return; }
    i -= WO4;
    if (i < WV4) { st_half4(&g_wah[i * 4], *(const float4*)&Wattn[i * 4]); return; }
    i -= WV4;
    if (i < WV4) { st_half4(&g_wouth[i * 4], *(const float4*)&Wout[i * 4]); }
}

// ---------------------------------------------------------------------------
// Multi-segment FP16 tensor-core GEMM, cp.async 3-stage pipeline.
// Each segment: C[M,N] = A[M,256] @ B[256,N] + bias[N] (+ add[M,N])
// A, B fp16; accumulate fp32; output float (Cf) or fp16 (Ch).
// Block 128x128, BK=32, 256 thr = 8 warps, warp tile 64x32, mma.m16n8k16.
// K = 256, N % 128 == 0 required.
// ---------------------------------------------------------------------------
#define GK      256
#define NIT     8            // GK / 32
#define NSTAGE  3
#define AS_H    40           // A smem row stride (halfs) = 80 B, conflict-free
#define BS_H    136          // B smem row stride (halfs) = 272 B, conflict-free
#define A_STG_B (128 * AS_H * 2)          // 10240 B
#define B_STG_B (32 * BS_H * 2)           // 8704 B
#define STG_B   (A_STG_B + B_STG_B)       // 18944 B
#define SMEM_BYTES (NSTAGE * STG_B)       // 56832 B

struct GemmSeg {
    const __half* A;
    const __half* B;
    const float*  bias;
    const float*  add;
    float*        Cf;
    __half*       Ch;
    int M, N, nbx, blk0;
};
struct GemmArgs { GemmSeg s[3]; };

__device__ __forceinline__ void cp16(uint32_t dst, const void* src) {
    asm volatile("cp.async.cg.shared.global [%0], [%1], 16;\n"
                 :: "r"(dst), "l"(src) : "memory");
}
__device__ __forceinline__ void cp_commit() {
    asm volatile("cp.async.commit_group;\n" ::: "memory");
}
template <int N> __device__ __forceinline__ void cp_wait() {
    asm volatile("cp.async.wait_group %0;\n" :: "n"(N) : "memory");
}
__device__ __forceinline__ uint32_t smem_u32(const void* p) {
    uint32_t a;
    asm("{ .reg .u64 t; cvta.to.shared.u64 t, %1; cvt.u32.u64 %0, t; }" : "=r"(a) : "l"(p));
    return a;
}

__global__ void __launch_bounds__(256)
gemm_h_multi(GemmArgs args)
{
    extern __shared__ char smem[];
    const uint32_t smb = smem_u32(smem);

    const int bi = blockIdx.x;
    const GemmSeg* sp = &args.s[0];
    if (bi >= args.s[2].blk0)      sp = &args.s[2];
    else if (bi >= args.s[1].blk0) sp = &args.s[1];
    const int local = bi - sp->blk0;
    const int M = sp->M, N = sp->N;
    const int block_row = (local / sp->nbx) * 128;
    const int block_col = (local % sp->nbx) * 128;

    const int tid  = threadIdx.x;
    const int wid  = tid >> 5;
    const int lane = tid & 31;
    const int warp_m = (wid >> 2) * 64;
    const int warp_n = (wid & 3) * 32;

    // ---- async load mappings ----
    // A: 128 rows x 32 halfs (64B); 2 threads/row, 2x16B each
    const int la_row  = tid >> 1;
    const int la_half = (tid & 1) * 16;       // half offset 0 / 16
    const int arow = min(block_row + la_row, M - 1);
    const __half* Asrc = sp->A + (size_t)arow * GK + la_half;
    const uint32_t Adst = smb + (la_row * AS_H + la_half) * 2;

    // B: 32 k-rows x 128 halfs (256B); 8 threads/row, 2x16B each
    const int lb_row = tid >> 3;
    const int lb_c   = (tid & 7) * 8;         // half offset within row
    const __half* Bsrc = sp->B + (size_t)lb_row * N + block_col + lb_c;
    const uint32_t Bdst = smb + A_STG_B + (lb_row * BS_H + lb_c) * 2;

    auto load_stage = [&](int s, int k0) {    // k0 in halfs (k-index)
        const uint32_t sa = Adst + s * STG_B;
        cp16(sa,      Asrc + k0);
        cp16(sa + 16, Asrc + k0 + 8);
        const uint32_t sb = Bdst + s * STG_B;
        const __half* bsrc = Bsrc + (size_t)k0 * N;
        cp16(sb,       bsrc);
        cp16(sb + 128, bsrc + 64);
    };

    // ---- ldmatrix lane offsets ----
    const int lg  = (lane >> 3) & 1;          // matrix row-half select
    const int lr  = lane & 7;
    const int lk  = lane >> 4;                // k-half / n-half select
    const int a_lane = (lr + lg * 8) * AS_H + lk * 8;            // halfs
    const int b_lane = (lr + lg * 8) * BS_H + lk * 8;            // halfs

    float acc[4][4][4] = {};

    load_stage(0, 0);  cp_commit();
    load_stage(1, 32); cp_commit();

    for (int i = 0; i < NIT; i++) {
        if (i + 2 < NIT) {
            load_stage((i + 2) % NSTAGE, (i + 2) * 32);
            cp_commit();
            cp_wait<2>();
        } else if (i == NIT - 2) {
            cp_wait<1>();
        } else {
            cp_wait<0>();
        }
        __syncthreads();

        const int s = i % NSTAGE;
        const uint32_t a_st = smb + s * STG_B + (warp_m * AS_H + a_lane) * 2;
        const uint32_t b_st = smb + s * STG_B + A_STG_B + (b_lane + warp_n) * 2;

        #pragma unroll
        for (int ks = 0; ks < 2; ks++) {
            uint32_t af[4][4], bf[4][2];
            #pragma unroll
            for (int mt = 0; mt < 4; mt++) {
                const uint32_t ad = a_st + mt * (16 * AS_H * 2) + ks * 32;
                asm volatile("ldmatrix.sync.aligned.m8n8.x4.shared.b16 "
                             "{%0,%1,%2,%3}, [%4];\n"
                             : "=r"(af[mt][0]), "=r"(af[mt][1]),
                               "=r"(af[mt][2]), "=r"(af[mt][3])
                             : "r"(ad));
            }
            #pragma unroll
            for (int np = 0; np < 2; np++) {
                const uint32_t bd = b_st + ks * (16 * BS_H * 2) + np * 32;
                asm volatile("ldmatrix.sync.aligned.m8n8.x4.trans.shared.b16 "
                             "{%0,%1,%2,%3}, [%4];\n"
                             : "=r"(bf[np * 2][0]), "=r"(bf[np * 2][1]),
                               "=r"(bf[np * 2 + 1][0]), "=r"(bf[np * 2 + 1][1])
                             : "r"(bd));
            }
            #pragma unroll
            for (int mt = 0; mt < 4; mt++)
                #pragma unroll
                for (int nt = 0; nt < 4; nt++) {
                    asm volatile(
                        "mma.sync.aligned.m16n8k16.row.col.f32.f16.f16.f32 "
                        "{%0,%1,%2,%3}, {%4,%5,%6,%7}, {%8,%9}, {%0,%1,%2,%3};\n"
                        : "+f"(acc[mt][nt][0]), "+f"(acc[mt][nt][1]),
                          "+f"(acc[mt][nt][2]), "+f"(acc[mt][nt][3])
                        : "r"(af[mt][0]), "r"(af[mt][1]), "r"(af[mt][2]), "r"(af[mt][3]),
                          "r"(bf[nt][0]), "r"(bf[nt][1]));
                }
        }
        __syncthreads();
    }

    // epilogue: c0/c1 at (row, col), c2/c3 at (row+8, col); col = 2*(lane&3)
    const int r0 = block_row + warp_m + (lane >> 2);
    const int c0 = block_col + warp_n + (lane & 3) * 2;
    const float* bias = sp->bias;
    #pragma unroll
    for (int mt = 0; mt < 4; mt++) {
        #pragma unroll
        for (int hh = 0; hh < 2; hh++) {
            const int row = r0 + mt * 16 + hh * 8;
            if (row >= M) continue;
            #pragma unroll
            for (int nt = 0; nt < 4; nt++) {
                const int col = c0 + nt * 8;
                float2 d;
                d.x = acc[mt][nt][hh * 2 + 0] + bias[col + 0];
                d.y = acc[mt][nt][hh * 2 + 1] + bias[col + 1];
                if (sp->add) {
                    const float2 ad = *(const float2*)&sp->add[(size_t)row * N + col];
                    d.x += ad.x; d.y += ad.y;
                }
                if (sp->Ch) {
                    *(__half2*)&sp->Ch[(size_t)row * N + col] = __floats2half2_rn(d.x, d.y);
                } else {
                    *(float2*)&sp->Cf[(size_t)row * N + col] = d;
                }
            }
        }
    }
}

// ---------------------------------------------------------------------------
// Deformable sampling + warp softmax. One warp per (query, head).
// fp16 value gathers, fp16 output.
// ---------------------------------------------------------------------------
__global__ void sampler_kernel(const float* __restrict__ refp)
{
    const int q    = blockIdx.x;
    const int h    = threadIdx.x >> 5;
    const int lane = threadIdx.x & 31;

    const int s = lane;
    const int l = s >> 3;
    const int p = s & 7;
    const int z = p & 3;

    const float ox = g_off[(size_t)q * 512 + h * 64 + s * 2 + 0];
    const float oy = g_off[(size_t)q * 512 + h * 64 + s * 2 + 1];
    const float rx = refp[(size_t)q * 8 + z * 2 + 0];
    const float ry = refp[(size_t)q * 8 + z * 2 + 1];
    const float x = rx * (float)c_W[l] + ox - 0.5f;
    const float y = ry * (float)c_H[l] + oy - 0.5f;

    float logit = g_logits[(size_t)q * 256 + h * 32 + s];
    float m = logit;
    #pragma unroll
    for (int o = 16; o > 0; o >>= 1) m = fmaxf(m, __shfl_xor_sync(0xffffffffu, m, o));
    float e = __expf(logit - m);
    float sum = e;
    #pragma unroll
    for (int o = 16; o > 0; o >>= 1) sum += __shfl_xor_sync(0xffffffffu, sum, o);
    const float w = e / sum;

    const int g  = lane >> 3;
    const int cl = (lane & 7) * 4;
    float4 acc = make_float4(0.f, 0.f, 0.f, 0.f);
    const size_t coff = (size_t)h * DHEAD + cl;

    #pragma unroll
    for (int it = 0; it < 8; it++) {
        const int s2 = it * 4 + g;
        const float xs = __shfl_sync(0xffffffffu, x, s2);
        const float ys = __shfl_sync(0xffffffffu, y, s2);
        const float ws = __shfl_sync(0xffffffffu, w, s2);
        const int   ls = s2 >> 3;
        const int   W2 = c_W[ls], H2 = c_H[ls];
        const int   base = c_start[ls];

        const float x0f = floorf(xs), y0f = floorf(ys);
        const int   x0 = (int)x0f,    y0 = (int)y0f;
        const float lx = xs - x0f,    ly = ys - y0f;

        const float w00 = ws * (1.f - lx) * (1.f - ly);
        const float w10 = ws * lx * (1.f - ly);
        const float w01 = ws * (1.f - lx) * ly;
        const float w11 = ws * lx * ly;

        const bool vx0 = (x0 >= 0) & (x0 < W2);
        const bool vx1 = (x0 + 1 >= 0) & (x0 + 1 < W2);
        const bool vy0 = (y0 >= 0) & (y0 < H2);
        const bool vy1 = (y0 + 1 >= 0) & (y0 + 1 < H2);

        const __half* row0 = g_vh + ((size_t)(base + y0 * W2 + x0) * EMB + coff);
        const __half* row1 = row0 + (size_t)W2 * EMB;

        #define CORNER(ptr, wgt) do {                                          \
            const uint2 u = *(const uint2*)(ptr);                              \
            const float2 f0 = __half22float2(*(const __half2*)&u.x);           \
            const float2 f1 = __half22float2(*(const __half2*)&u.y);           \
            acc.x = fmaf(wgt, f0.x, acc.x); acc.y = fmaf(wgt, f0.y, acc.y);    \
            acc.z = fmaf(wgt, f1.x, acc.z); acc.w = fmaf(wgt, f1.y, acc.w);    \
        } while (0)

        if (vy0) {
            if (vx0) CORNER(row0, w00);
            if (vx1) CORNER(row0 + EMB, w10);
        }
        if (vy1) {
            if (vx0) CORNER(row1, w01);
            if (vx1) CORNER(row1 + EMB, w11);
        }
        #undef CORNER
    }

    #pragma unroll
    for (int o = 8; o < 32; o <<= 1) {
        acc.x += __shfl_xor_sync(0xffffffffu, acc.x, o);
        acc.y += __shfl_xor_sync(0xffffffffu, acc.y, o);
        acc.z += __shfl_xor_sync(0xffffffffu, acc.z, o);
        acc.w += __shfl_xor_sync(0xffffffffu, acc.w, o);
    }
    if (lane < 8)
        st_half4(&g_samph[(size_t)q * EMB + h * DHEAD + cl], acc);
}

// ---------------------------------------------------------------------------
// Launch
// ---------------------------------------------------------------------------
static void* sym_addr(const void* symbol) {
    void* p = nullptr;
    cudaGetSymbolAddress(&p, symbol);
    return p;
}

extern "C" void kernel_launch(void* const* d_in, const int* in_sizes, int n_in,
                              void* d_out, int out_size)
{
    const float* query  = (const float*)d_in[0];
    const float* value  = (const float*)d_in[1];
    const float* qpos   = (const float*)d_in[2];
    const float* refp   = (const float*)d_in[3];
    // d_in[4] spatial_shapes: static, baked into constants
    const float* W_off  = (const float*)d_in[5];
    const float* b_off  = (const float*)d_in[6];
    const float* W_attn = (const float*)d_in[7];
    const float* b_attn = (const float*)d_in[8];
    const float* W_val  = (const float*)d_in[9];
    const float* b_val  = (const float*)d_in[10];
    const float* W_out  = (const float*)d_in[11];
    const float* b_out  = (const float*)d_in[12];
    float* out = (float*)d_out;

    __half* qh   = (__half*)sym_addr(g_qh);
    __half* valh = (__half*)sym_addr(g_valh);
    __half* vhb  = (__half*)sym_addr(g_vh);
    __half* samph= (__half*)sym_addr(g_samph);
    float*  offb = (float*)sym_addr(g_off);
    float*  logb = (float*)sym_addr(g_logits);
    __half* wvh  = (__half*)sym_addr(g_wvh);
    __half* woh  = (__half*)sym_addr(g_woh);
    __half* wah  = (__half*)sym_addr(g_wah);
    __half* wouth= (__half*)sym_addr(g_wouth);

    cudaFuncSetAttribute(gemm_h_multi,
                         cudaFuncAttributeMaxDynamicSharedMemorySize, SMEM_BYTES);

    // 0. convert inputs + weights, q = query + qpos
    prep_kernel<<<(PREP_TOTAL + 255) / 256, 256>>>(value, query, qpos,
                                                   W_val, W_off, W_attn, W_out);

    const int nbv = ((NV + 127) / 128) * 2;   // 306
    const int nbo = ((NQ + 127) / 128) * 4;   // 316
    const int nbl = ((NQ + 127) / 128) * 2;   // 158

    // 1. merged front GEMMs: v-proj (fp16 out), off-proj, logits
    {
        GemmArgs ga;
        ga.s[0] = {valh, wvh, b_val,  nullptr, nullptr, vhb, NV, 256, 2, 0};
        ga.s[1] = {qh,   woh, b_off,  nullptr, offb, nullptr, NQ, 512, 4, nbv};
        ga.s[2] = {qh,   wah, b_attn, nullptr, logb, nullptr, NQ, 256, 2, nbv + nbo};
        gemm_h_multi<<<nbv + nbo + nbl, 256, SMEM_BYTES>>>(ga);
    }

    // 2. deformable sampling (softmax fused in-warp)
    sampler_kernel<<<NQ, 256>>>(refp);

    // 3. out = samp @ W_out + b_out + query (residual)
    {
        GemmArgs ga;
        ga.s[0] = {samph, wouth, b_out, query, out, nullptr, NQ, 256, 2, 0};
        ga.s[1] = ga.s[0]; ga.s[1].blk0 = 1 << 30;
        ga.s[2] = ga.s[0]; ga.s[2].blk0 = 1 << 30;
        gemm_h_multi<<<nbl, 256, SMEM_BYTES>>>(ga);
    }
}